// round 2
// baseline (speedup 1.0000x reference)
#include <cuda_runtime.h>
#include <math.h>

// Problem constants (fixed by the reference)
#define BATCH 1000
#define NUEc  4
#define NBSc  4
#define Kc    500
#define Mc    500
#define Nc    1000
#define NSYMc 250
#define NT    (BATCH*NSYMc)   // 250000 symbol-times
#define NCW   (BATCH*NUEc)    // 4000 codewords
#define NE    2000            // LDPC edges

// ---------------- device scratch (static, no allocation) ----------------
__device__ float2 g_xf[NT*NUEc];        // 8 MB  transmitted symbols, [t][u]
__device__ float  g_Lch[NCW*Nc];        // 16 MB channel LLRs, [cw][n]
__device__ int    g_voff[Nc+1];
__device__ int    g_vedges[NE];
__device__ int    g_coff[Mc+1];
__device__ int    g_cedges[NE];
__device__ float  g_no;

// 16-QAM constellation: p bits (MSB..LSB) = (b0,b1,b2,b3)
// re = (1-2b0)*(2-(1-2b2))/sqrt(10), im = (1-2b1)*(2-(1-2b3))/sqrt(10)
#define QA 0.31622776601683794f
#define QB 0.9486832980505138f
__constant__ float QRE[16] = { QA, QA, QB, QB, QA, QA, QB, QB,
                              -QA,-QA,-QB,-QB,-QA,-QA,-QB,-QB};
__constant__ float QIM[16] = { QA, QB, QA, QB,-QA,-QB,-QA,-QB,
                               QA, QB, QA, QB,-QA,-QB,-QA,-QB};

// ---------------- complex helpers ----------------
__device__ __forceinline__ float2 cmul(float2 a, float2 b){
    return make_float2(a.x*b.x - a.y*b.y, a.x*b.y + a.y*b.x);
}
// conj(a)*b
__device__ __forceinline__ float2 cjmul(float2 a, float2 b){
    return make_float2(a.x*b.x + a.y*b.y, a.x*b.y - a.y*b.x);
}
__device__ __forceinline__ float2 csub(float2 a, float2 b){
    return make_float2(a.x-b.x, a.y-b.y);
}
__device__ __forceinline__ float2 cadd(float2 a, float2 b){
    return make_float2(a.x+b.x, a.y+b.y);
}

// ---------------- k0a: counts + offsets + noise scalar ----------------
__global__ void __launch_bounds__(1024) k0a(const float* __restrict__ ebno,
                                            const int* __restrict__ cn,
                                            const int* __restrict__ vnn)
{
    __shared__ int vc[1024];
    __shared__ int cc[512];
    int tid = threadIdx.x;
    vc[tid] = 0;
    if (tid < 512) cc[tid] = 0;
    __syncthreads();
    for (int e = tid; e < NE; e += 1024){
        atomicAdd(&vc[vnn[e]], 1);
        atomicAdd(&cc[cn[e]], 1);
    }
    __syncthreads();
    // inclusive scan over vc (1024)
    for (int ofs = 1; ofs < 1024; ofs <<= 1){
        int t = 0;
        if (tid >= ofs) t = vc[tid-ofs];
        __syncthreads();
        vc[tid] += t;
        __syncthreads();
    }
    // inclusive scan over cc (512)
    for (int ofs = 1; ofs < 512; ofs <<= 1){
        int t = 0;
        if (tid < 512 && tid >= ofs) t = cc[tid-ofs];
        __syncthreads();
        if (tid < 512) cc[tid] += t;
        __syncthreads();
    }
    if (tid == 0){
        g_voff[0] = 0;
        g_coff[0] = 0;
        float e = ebno[0];
        g_no = 1.0f / (exp10f(e*0.1f) * 4.0f * 0.5f);
    }
    if (tid < Nc) g_voff[tid+1] = vc[tid];
    if (tid < Mc) g_coff[tid+1] = cc[tid];
}

// ---------------- k0b: deterministic CSR fill (stable, edge-ascending) ----------------
__global__ void __launch_bounds__(256) k0b(const int* __restrict__ cn,
                                           const int* __restrict__ vnn)
{
    __shared__ int svn[NE];
    __shared__ int scn[NE];
    int tid = threadIdx.x;
    for (int i = tid; i < NE; i += 256){ svn[i] = vnn[i]; scn[i] = cn[i]; }
    __syncthreads();
    int e = blockIdx.x*256 + tid;
    if (e < NE){
        int v = svn[e], c = scn[e];
        int rv = 0, rc = 0;
        for (int e2 = 0; e2 < e; e2++){
            rv += (svn[e2] == v);
            rc += (scn[e2] == c);
        }
        g_vedges[g_voff[v] + rv] = e;
        g_cedges[g_coff[c] + rc] = e;
    }
}

// ---------------- k1: encode (sparse XOR) + modulate + bf output ----------------
__global__ void __launch_bounds__(256) k1(const int* __restrict__ b,
                                          const int* __restrict__ cn,
                                          const int* __restrict__ vnn,
                                          float* __restrict__ out)
{
    int cw = blockIdx.x, tid = threadIdx.x;
    __shared__ int bits[Nc];
    for (int i = tid; i < Kc; i += 256){
        int bv = b[cw*Kc + i];
        bits[i] = bv;
        bits[Kc + i] = 0;
        out[cw*Kc + i] = (float)bv;   // bf output
    }
    __syncthreads();
    for (int e = tid; e < NE; e += 256){
        int v = vnn[e];
        if (v < Kc && bits[v]) atomicXor(&bits[Kc + cn[e]], 1);
    }
    __syncthreads();
    int bb = cw >> 2, u = cw & 3;
    for (int s = tid; s < NSYMc; s += 256){
        int idx = bits[4*s]*8 + bits[4*s+1]*4 + bits[4*s+2]*2 + bits[4*s+3];
        g_xf[(bb*NSYMc + s)*NUEc + u] = make_float2(QRE[idx], QIM[idx]);
    }
}

// ---------------- k2: channel + LMMSE (4x4 complex GJ) + max-log demap ----------------
__global__ void __launch_bounds__(128) k2(const float* __restrict__ hre,
                                          const float* __restrict__ him,
                                          const float* __restrict__ nre,
                                          const float* __restrict__ nim)
{
    int t = blockIdx.x*blockDim.x + threadIdx.x;
    if (t >= NT) return;
    float no = g_no;
    const float inv_s2 = 0.70710678118654752f;

    float2 h[4][4];
    #pragma unroll
    for (int i = 0; i < 4; i++){
        float4 r = ((const float4*)hre)[t*4 + i];
        float4 m = ((const float4*)him)[t*4 + i];
        h[i][0] = make_float2(r.x*inv_s2, m.x*inv_s2);
        h[i][1] = make_float2(r.y*inv_s2, m.y*inv_s2);
        h[i][2] = make_float2(r.z*inv_s2, m.z*inv_s2);
        h[i][3] = make_float2(r.w*inv_s2, m.w*inv_s2);
    }

    float2 x[4];
    #pragma unroll
    for (int u = 0; u < 4; u++) x[u] = g_xf[t*4 + u];

    float sw = sqrtf(no*0.5f);
    float2 y[4];
    #pragma unroll
    for (int i = 0; i < 4; i++){
        float2 acc = make_float2(nre[t*4+i]*sw, nim[t*4+i]*sw);
        #pragma unroll
        for (int u = 0; u < 4; u++) acc = cadd(acc, cmul(h[i][u], x[u]));
        y[i] = acc;
    }

    // A = h h^H + no I  (Hermitian)
    float2 Mt[4][4];
    #pragma unroll
    for (int i = 0; i < 4; i++){
        #pragma unroll
        for (int j = i; j < 4; j++){
            if (i == j){
                float s = no;
                #pragma unroll
                for (int u = 0; u < 4; u++)
                    s += h[i][u].x*h[i][u].x + h[i][u].y*h[i][u].y;
                Mt[i][i] = make_float2(s, 0.f);
            } else {
                float2 s = make_float2(0.f, 0.f);
                #pragma unroll
                for (int u = 0; u < 4; u++)
                    s = cadd(s, cjmul(h[j][u], h[i][u]));  // h[i][u]*conj(h[j][u])
                Mt[i][j] = s;
                Mt[j][i] = make_float2(s.x, -s.y);
            }
        }
    }

    // RHS = [h | y],  Gauss-Jordan (A is HPD -> no pivoting needed)
    float2 B[4][5];
    #pragma unroll
    for (int i = 0; i < 4; i++){
        #pragma unroll
        for (int u = 0; u < 4; u++) B[i][u] = h[i][u];
        B[i][4] = y[i];
    }
    #pragma unroll
    for (int k = 0; k < 4; k++){
        float2 p = Mt[k][k];
        float is = 1.0f/(p.x*p.x + p.y*p.y);
        float2 ip = make_float2(p.x*is, -p.y*is);
        #pragma unroll
        for (int j = 0; j < 4; j++) Mt[k][j] = cmul(Mt[k][j], ip);
        #pragma unroll
        for (int c = 0; c < 5; c++) B[k][c] = cmul(B[k][c], ip);
        #pragma unroll
        for (int i = 0; i < 4; i++){
            if (i == k) continue;
            float2 f = Mt[i][k];
            #pragma unroll
            for (int j = 0; j < 4; j++) Mt[i][j] = csub(Mt[i][j], cmul(f, Mt[k][j]));
            #pragma unroll
            for (int c = 0; c < 5; c++) B[i][c] = csub(B[i][c], cmul(f, B[k][c]));
        }
    }

    int bb = t / NSYMc;
    int s  = t - bb*NSYMc;

    #pragma unroll
    for (int u = 0; u < 4; u++){
        float2 xraw = make_float2(0.f, 0.f);
        float2 g    = make_float2(0.f, 0.f);
        #pragma unroll
        for (int i = 0; i < 4; i++){
            xraw = cadd(xraw, cjmul(h[i][u], B[i][4]));
            g    = cadd(g,    cjmul(h[i][u], B[i][u]));
        }
        float d = g.x;
        float xr = xraw.x / d;
        float xi = xraw.y / d;
        float nvar = fmaxf(1.0f/d - 1.0f, 1e-12f);

        float min0[4], min1[4];
        #pragma unroll
        for (int k = 0; k < 4; k++){ min0[k] = 1e30f; min1[k] = 1e30f; }
        #pragma unroll
        for (int p = 0; p < 16; p++){
            float dr = xr - QRE[p];
            float di = xi - QIM[p];
            float dd = dr*dr + di*di;
            #pragma unroll
            for (int k = 0; k < 4; k++){
                if ((p >> (3-k)) & 1) min1[k] = fminf(min1[k], dd);
                else                  min0[k] = fminf(min0[k], dd);
            }
        }
        int cw = bb*NUEc + u;
        int base = cw*Nc + 4*s;
        #pragma unroll
        for (int k = 0; k < 4; k++)
            g_Lch[base + k] = (min1[k] - min0[k]) / nvar;
    }
}

// ---------------- k3: 5-iteration sum-product BP, all state in smem ----------------
__global__ void __launch_bounds__(256) k3(const int* __restrict__ vnn,
                                          float* __restrict__ out)
{
    int cw = blockIdx.x, tid = threadIdx.x;
    __shared__ float Ls[Nc];
    __shared__ float vt[Nc];
    __shared__ float c2v[NE];
    __shared__ float ts[NE];

    for (int i = tid; i < Nc; i += 256) Ls[i] = g_Lch[cw*Nc + i];
    for (int i = tid; i < NE; i += 256) c2v[i] = 0.f;
    __syncthreads();

    for (int it = 0; it < 5; it++){
        // variable update: vtot = Lch + sum incident c2v
        for (int v = tid; v < Nc; v += 256){
            float s = Ls[v];
            int o0 = g_voff[v], o1 = g_voff[v+1];
            for (int o = o0; o < o1; o++) s += c2v[g_vedges[o]];
            vt[v] = s;
        }
        __syncthreads();
        // check update
        for (int c = tid; c < Mc; c += 256){
            int o0 = g_coff[c], o1 = g_coff[c+1];
            float prod = 1.f;
            for (int o = o0; o < o1; o++){
                int e = g_cedges[o];
                float m = vt[vnn[e]] - c2v[e];
                float a = fminf(fmaxf(0.5f*m, -9.9f), 9.9f);
                float tt = tanhf(a);
                tt = (tt >= 0.f) ? fmaxf(tt, 1e-7f) : fminf(tt, -1e-7f);
                ts[e] = tt;
                prod *= tt;
            }
            for (int o = o0; o < o1; o++){
                int e = g_cedges[o];
                float r = prod / ts[e];
                r = fminf(fmaxf(r, -0.999999f), 0.999999f);
                c2v[e] = 2.f*atanhf(r);
            }
        }
        __syncthreads();
    }
    // final total + hard decision on info bits
    for (int v = tid; v < Kc; v += 256){
        float s = Ls[v];
        int o0 = g_voff[v], o1 = g_voff[v+1];
        for (int o = o0; o < o1; o++) s += c2v[g_vedges[o]];
        out[NCW*Kc + cw*Kc + v] = (s < 0.f) ? 1.f : 0.f;
    }
}

// ---------------- launch ----------------
extern "C" void kernel_launch(void* const* d_in, const int* in_sizes, int n_in,
                              void* d_out, int out_size)
{
    // inputs: [batch_size?], ebno_db, b, P, cn_idx, vn_idx, h_re, h_im, noise_re, noise_im
    int ofs = (n_in >= 10) ? 1 : 0;
    const float* ebno = (const float*)d_in[ofs + 0];
    const int*   b    = (const int*)  d_in[ofs + 1];
    // P (d_in[ofs+2]) unused — adjacency comes from cn/vn edge lists
    const int*   cn   = (const int*)  d_in[ofs + 3];
    const int*   vnn  = (const int*)  d_in[ofs + 4];
    const float* hre  = (const float*)d_in[ofs + 5];
    const float* him  = (const float*)d_in[ofs + 6];
    const float* nre  = (const float*)d_in[ofs + 7];
    const float* nim  = (const float*)d_in[ofs + 8];
    float* out = (float*)d_out;

    k0a<<<1, 1024>>>(ebno, cn, vnn);
    k0b<<<(NE + 255)/256, 256>>>(cn, vnn);
    k1 <<<NCW, 256>>>(b, cn, vnn, out);
    k2 <<<(NT + 127)/128, 128>>>(hre, him, nre, nim);
    k3 <<<NCW, 256>>>(vnn, out);
}

// round 4
// speedup vs baseline: 2.3070x; 2.3070x over previous
#include <cuda_runtime.h>
#include <math.h>

// Problem constants (fixed by the reference)
#define BATCH 1000
#define NUEc  4
#define NBSc  4
#define Kc    500
#define Mc    500
#define Nc    1000
#define NSYMc 250
#define NT    (BATCH*NSYMc)   // 250000 symbol-times
#define NCW   (BATCH*NUEc)    // 4000 codewords
#define NE    2000            // LDPC edges total
#define NIE   1500            // info edges (e < 1500); parity edges are e=1500+c

// ---------------- device scratch (static, no allocation) ----------------
__device__ float2 g_xf[NT*NUEc];        // 8 MB  transmitted symbols, [t][u]
__device__ float  g_Lch[NCW*Nc];        // 16 MB channel LLRs, [cw][n]
__device__ int    g_ioff[Mc+1];         // per-check info-edge CSR offsets
__device__ int    g_ivar[NIE];          // check-major slot -> info var index
__device__ int    g_ichk[NIE];          // check-major slot -> check index
__device__ int    g_vslot[Kc*3];        // info var -> its 3 check-major slots
__device__ float  g_no;

// 16-QAM constellation: p bits (MSB..LSB) = (b0,b1,b2,b3)
#define QA 0.31622776601683794f
#define QB 0.9486832980505138f
__constant__ float QRE[16] = { QA, QA, QB, QB, QA, QA, QB, QB,
                              -QA,-QA,-QB,-QB,-QA,-QA,-QB,-QB};
__constant__ float QIM[16] = { QA, QB, QA, QB,-QA,-QB,-QA,-QB,
                               QA, QB, QA, QB,-QA,-QB,-QA,-QB};

// ---------------- complex helpers ----------------
__device__ __forceinline__ float2 cmul(float2 a, float2 b){
    return make_float2(a.x*b.x - a.y*b.y, a.x*b.y + a.y*b.x);
}
__device__ __forceinline__ float2 cjmul(float2 a, float2 b){   // conj(a)*b
    return make_float2(a.x*b.x + a.y*b.y, a.x*b.y - a.y*b.x);
}
__device__ __forceinline__ float2 csub(float2 a, float2 b){
    return make_float2(a.x-b.x, a.y-b.y);
}
__device__ __forceinline__ float2 cadd(float2 a, float2 b){
    return make_float2(a.x+b.x, a.y+b.y);
}

// tanh(m/2) with reference clipping/eps semantics
__device__ __forceinline__ float tanh_half(float m){
    m = fminf(fmaxf(m, -19.8f), 19.8f);
    float e = __expf(m);
    float t = __fdividef(e - 1.0f, e + 1.0f);
    return (t >= 0.0f) ? fmaxf(t, 1e-7f) : fminf(t, -1e-7f);
}

// ---------------- k0a: per-check info-edge counts -> offsets, noise scalar ----------------
__global__ void __launch_bounds__(512) k0a(const float* __restrict__ ebno,
                                           const int* __restrict__ cn)
{
    __shared__ int cc[512];
    int tid = threadIdx.x;
    cc[tid] = 0;
    __syncthreads();
    for (int e = tid; e < NIE; e += 512) atomicAdd(&cc[cn[e]], 1);
    __syncthreads();
    for (int ofs = 1; ofs < 512; ofs <<= 1){
        int t = 0;
        if (tid >= ofs) t = cc[tid-ofs];
        __syncthreads();
        cc[tid] += t;
        __syncthreads();
    }
    if (tid == 0){
        g_ioff[0] = 0;
        float e = ebno[0];
        g_no = 1.0f / (exp10f(e*0.1f) * 4.0f * 0.5f);
    }
    if (tid < Mc) g_ioff[tid+1] = cc[tid];
}

// ---------------- k0b: deterministic CSR fill (stable, edge-ascending) ----------------
__global__ void __launch_bounds__(256) k0b(const int* __restrict__ cn,
                                           const int* __restrict__ vnn)
{
    __shared__ int svn[NIE];
    __shared__ int scn[NIE];
    int tid = threadIdx.x;
    for (int i = tid; i < NIE; i += 256){ svn[i] = vnn[i]; scn[i] = cn[i]; }
    __syncthreads();
    int e = blockIdx.x*256 + tid;
    if (e < NIE){
        int c = scn[e], v = svn[e];
        int rc = 0, rv = 0;
        for (int e2 = 0; e2 < e; e2++){
            rc += (scn[e2] == c);
            rv += (svn[e2] == v);
        }
        int slot = g_ioff[c] + rc;
        g_ivar[slot] = v;
        g_ichk[slot] = c;
        g_vslot[v*3 + rv] = slot;
    }
}

// ---------------- k1: encode (sparse XOR) + modulate + bf output ----------------
__global__ void __launch_bounds__(256) k1(const int* __restrict__ b,
                                          const int* __restrict__ cn,
                                          const int* __restrict__ vnn,
                                          float* __restrict__ out)
{
    int cw = blockIdx.x, tid = threadIdx.x;
    __shared__ int bits[Nc];
    for (int i = tid; i < Kc; i += 256){
        int bv = b[cw*Kc + i];
        bits[i] = bv;
        bits[Kc + i] = 0;
        out[cw*Kc + i] = (float)bv;   // bf output
    }
    __syncthreads();
    for (int e = tid; e < NIE; e += 256){
        int v = vnn[e];
        if (bits[v]) atomicXor(&bits[Kc + cn[e]], 1);
    }
    __syncthreads();
    int bb = cw >> 2, u = cw & 3;
    for (int s = tid; s < NSYMc; s += 256){
        int idx = bits[4*s]*8 + bits[4*s+1]*4 + bits[4*s+2]*2 + bits[4*s+3];
        g_xf[(bb*NSYMc + s)*NUEc + u] = make_float2(QRE[idx], QIM[idx]);
    }
}

// ---------------- k2: channel + LMMSE (4x4 complex GJ) + max-log demap ----------------
__global__ void __launch_bounds__(128) k2(const float* __restrict__ hre,
                                          const float* __restrict__ him,
                                          const float* __restrict__ nre,
                                          const float* __restrict__ nim)
{
    int t = blockIdx.x*blockDim.x + threadIdx.x;
    if (t >= NT) return;
    float no = g_no;
    const float inv_s2 = 0.70710678118654752f;

    float2 h[4][4];
    #pragma unroll
    for (int i = 0; i < 4; i++){
        float4 r = ((const float4*)hre)[t*4 + i];
        float4 m = ((const float4*)him)[t*4 + i];
        h[i][0] = make_float2(r.x*inv_s2, m.x*inv_s2);
        h[i][1] = make_float2(r.y*inv_s2, m.y*inv_s2);
        h[i][2] = make_float2(r.z*inv_s2, m.z*inv_s2);
        h[i][3] = make_float2(r.w*inv_s2, m.w*inv_s2);
    }

    float2 x[4];
    #pragma unroll
    for (int u = 0; u < 4; u++) x[u] = g_xf[t*4 + u];

    float sw = sqrtf(no*0.5f);
    float2 y[4];
    #pragma unroll
    for (int i = 0; i < 4; i++){
        float2 acc = make_float2(nre[t*4+i]*sw, nim[t*4+i]*sw);
        #pragma unroll
        for (int u = 0; u < 4; u++) acc = cadd(acc, cmul(h[i][u], x[u]));
        y[i] = acc;
    }

    // A = h h^H + no I  (Hermitian)
    float2 Mt[4][4];
    #pragma unroll
    for (int i = 0; i < 4; i++){
        #pragma unroll
        for (int j = i; j < 4; j++){
            if (i == j){
                float s = no;
                #pragma unroll
                for (int u = 0; u < 4; u++)
                    s += h[i][u].x*h[i][u].x + h[i][u].y*h[i][u].y;
                Mt[i][i] = make_float2(s, 0.f);
            } else {
                float2 s = make_float2(0.f, 0.f);
                #pragma unroll
                for (int u = 0; u < 4; u++)
                    s = cadd(s, cjmul(h[j][u], h[i][u]));
                Mt[i][j] = s;
                Mt[j][i] = make_float2(s.x, -s.y);
            }
        }
    }

    // RHS = [h | y],  Gauss-Jordan (A is HPD -> no pivoting needed)
    float2 B[4][5];
    #pragma unroll
    for (int i = 0; i < 4; i++){
        #pragma unroll
        for (int u = 0; u < 4; u++) B[i][u] = h[i][u];
        B[i][4] = y[i];
    }
    #pragma unroll
    for (int k = 0; k < 4; k++){
        float2 p = Mt[k][k];
        float is = 1.0f/(p.x*p.x + p.y*p.y);
        float2 ip = make_float2(p.x*is, -p.y*is);
        #pragma unroll
        for (int j = 0; j < 4; j++) Mt[k][j] = cmul(Mt[k][j], ip);
        #pragma unroll
        for (int c = 0; c < 5; c++) B[k][c] = cmul(B[k][c], ip);
        #pragma unroll
        for (int i = 0; i < 4; i++){
            if (i == k) continue;
            float2 f = Mt[i][k];
            #pragma unroll
            for (int j = 0; j < 4; j++) Mt[i][j] = csub(Mt[i][j], cmul(f, Mt[k][j]));
            #pragma unroll
            for (int c = 0; c < 5; c++) B[i][c] = csub(B[i][c], cmul(f, B[k][c]));
        }
    }

    int bb = t / NSYMc;
    int s  = t - bb*NSYMc;

    #pragma unroll
    for (int u = 0; u < 4; u++){
        float2 xraw = make_float2(0.f, 0.f);
        float2 g    = make_float2(0.f, 0.f);
        #pragma unroll
        for (int i = 0; i < 4; i++){
            xraw = cadd(xraw, cjmul(h[i][u], B[i][4]));
            g    = cadd(g,    cjmul(h[i][u], B[i][u]));
        }
        float d = g.x;
        float xr = xraw.x / d;
        float xi = xraw.y / d;
        float nvar = fmaxf(1.0f/d - 1.0f, 1e-12f);

        float min0[4], min1[4];
        #pragma unroll
        for (int k = 0; k < 4; k++){ min0[k] = 1e30f; min1[k] = 1e30f; }
        #pragma unroll
        for (int p = 0; p < 16; p++){
            float dr = xr - QRE[p];
            float di = xi - QIM[p];
            float dd = dr*dr + di*di;
            #pragma unroll
            for (int k = 0; k < 4; k++){
                if ((p >> (3-k)) & 1) min1[k] = fminf(min1[k], dd);
                else                  min0[k] = fminf(min0[k], dd);
            }
        }
        int cw = bb*NUEc + u;
        int base = cw*Nc + 4*s;
        #pragma unroll
        for (int k = 0; k < 4; k++)
            g_Lch[base + k] = (min1[k] - min0[k]) / nvar;
    }
}

// ---------------- k3: 5-iteration sum-product BP, edge-parallel, smem state ----------------
__global__ void __launch_bounds__(256) k3(float* __restrict__ out)
{
    int cw = blockIdx.x, tid = threadIdx.x;
    __shared__ float Ls[Kc];      // info-bit channel LLRs
    __shared__ float tpar[Mc];    // fixed parity-edge tanh per check
    __shared__ float vt[Kc];      // variable totals (info vars only)
    __shared__ float pc[Mc];      // per-check tanh product
    __shared__ float c2v[NIE];    // check->var messages, check-major slots
    __shared__ float ts[NIE];     // per-slot tanh

    const float* L = g_Lch + (size_t)cw*Nc;
    for (int i = tid; i < Kc; i += 256) Ls[i] = L[i];
    // parity var has degree 1: its v->c message is Lch[K+c] every iteration
    for (int c = tid; c < Mc; c += 256) tpar[c] = tanh_half(L[Kc + c]);
    for (int i = tid; i < NIE; i += 256) c2v[i] = 0.f;
    __syncthreads();

    #pragma unroll 1
    for (int it = 0; it < 5; it++){
        // variable update (info vars, fixed degree 3)
        for (int v = tid; v < Kc; v += 256){
            int s0 = __ldg(&g_vslot[v*3+0]);
            int s1 = __ldg(&g_vslot[v*3+1]);
            int s2 = __ldg(&g_vslot[v*3+2]);
            vt[v] = Ls[v] + c2v[s0] + c2v[s1] + c2v[s2];
        }
        __syncthreads();
        // pass 1: per-slot tanh (evenly distributed)
        for (int s = tid; s < NIE; s += 256){
            float m = vt[__ldg(&g_ivar[s])] - c2v[s];
            ts[s] = tanh_half(m);
        }
        __syncthreads();
        // pass 2: per-check product (cheap multiplies only)
        for (int c = tid; c < Mc; c += 256){
            int o0 = __ldg(&g_ioff[c]), o1 = __ldg(&g_ioff[c+1]);
            float p = tpar[c];
            for (int o = o0; o < o1; o++) p *= ts[o];
            pc[c] = p;
        }
        __syncthreads();
        // pass 3: per-slot extrinsic + atanh (evenly distributed)
        for (int s = tid; s < NIE; s += 256){
            float r = __fdividef(pc[__ldg(&g_ichk[s])], ts[s]);
            r = fminf(fmaxf(r, -0.999999f), 0.999999f);
            c2v[s] = __logf(__fdividef(1.0f + r, 1.0f - r));   // = 2*atanh(r)
        }
        __syncthreads();
    }
    // final totals + hard decision on info bits
    for (int v = tid; v < Kc; v += 256){
        int s0 = __ldg(&g_vslot[v*3+0]);
        int s1 = __ldg(&g_vslot[v*3+1]);
        int s2 = __ldg(&g_vslot[v*3+2]);
        float s = Ls[v] + c2v[s0] + c2v[s1] + c2v[s2];
        out[(size_t)NCW*Kc + (size_t)cw*Kc + v] = (s < 0.f) ? 1.f : 0.f;
    }
}

// ---------------- launch ----------------
extern "C" void kernel_launch(void* const* d_in, const int* in_sizes, int n_in,
                              void* d_out, int out_size)
{
    int ofs = (n_in >= 10) ? 1 : 0;
    const float* ebno = (const float*)d_in[ofs + 0];
    const int*   b    = (const int*)  d_in[ofs + 1];
    // P (d_in[ofs+2]) unused — adjacency comes from cn/vn edge lists
    const int*   cn   = (const int*)  d_in[ofs + 3];
    const int*   vnn  = (const int*)  d_in[ofs + 4];
    const float* hre  = (const float*)d_in[ofs + 5];
    const float* him  = (const float*)d_in[ofs + 6];
    const float* nre  = (const float*)d_in[ofs + 7];
    const float* nim  = (const float*)d_in[ofs + 8];
    float* out = (float*)d_out;

    k0a<<<1, 512>>>(ebno, cn);
    k0b<<<(NIE + 255)/256, 256>>>(cn, vnn);
    k1 <<<NCW, 256>>>(b, cn, vnn, out);
    k2 <<<(NT + 127)/128, 128>>>(hre, him, nre, nim);
    k3 <<<NCW, 256>>>(out);
}